// round 11
// baseline (speedup 1.0000x reference)
#include <cuda_runtime.h>
#include <cuda_bf16.h>
#include <math.h>
#include <cstdint>

// ---------------- problem dims ----------------
#define Bv   2
#define Sv   1024
#define Dv   1024
#define Hh   16
#define HDv  64
#define Tv   1024
#define FFv  4096
#define Lv   8
#define Vv   32000
#define BS   (Bv*Sv)     // 2048
#define BHv  (Bv*Hh)     // 32

// ============ PTX helpers (baseline PTX only: sm_80-class features) ============
__device__ __forceinline__ uint32_t smem_to_u32(const void* p) {
    uint32_t a;
    asm("{ .reg .u64 t; cvta.to.shared.u64 t, %1; cvt.u32.u64 %0, t; }" : "=r"(a) : "l"(p));
    return a;
}
#define CP_ASYNC16(dst, src) \
    asm volatile("cp.async.cg.shared.global [%0], [%1], 16;" :: "r"(dst), "l"(src))
#define CP_COMMIT() asm volatile("cp.async.commit_group;" ::: "memory")
#define CP_WAIT1()  asm volatile("cp.async.wait_group 1;" ::: "memory")
#define CP_WAIT0()  asm volatile("cp.async.wait_group 0;" ::: "memory")
#define LDSM_X4(R0, R1, R2, R3, ADDR) \
    asm volatile("ldmatrix.sync.aligned.m8n8.x4.shared.b16 {%0,%1,%2,%3}, [%4];" \
        : "=r"(R0), "=r"(R1), "=r"(R2), "=r"(R3) : "r"(ADDR))
#define MMA_BF16(D, A0, A1, A2, A3, B0, B1) \
    asm volatile("mma.sync.aligned.m16n8k16.row.col.f32.bf16.bf16.f32 " \
        "{%0,%1,%2,%3},{%4,%5,%6,%7},{%8,%9},{%0,%1,%2,%3};" \
        : "+f"((D)[0]), "+f"((D)[1]), "+f"((D)[2]), "+f"((D)[3]) \
        : "r"(A0), "r"(A1), "r"(A2), "r"(A3), "r"(B0), "r"(B1))

// ---------------- scratch (device globals; no allocations, no host API) ----------------
__device__ float g_X [BS*Dv];
__device__ float g_U [BS*3*Tv];
__device__ float g_P [(size_t)BHv*Sv*Sv];           // fp32 scores

// attention bf16 hi/lo buffers
__device__ __nv_bfloat16 g_Qh[BHv*Sv*HDv], g_Ql[BHv*Sv*HDv];
__device__ __nv_bfloat16 g_Kh[BHv*Sv*HDv], g_Kl[BHv*Sv*HDv];
__device__ __nv_bfloat16 g_Vh[BHv*Sv*HDv], g_Vl[BHv*Sv*HDv];
__device__ __nv_bfloat16 g_VTh[BHv*Sv*HDv], g_VTl[BHv*Sv*HDv];   // [bh][d][s]
__device__ __nv_bfloat16 g_Phi[(size_t)BHv*Sv*Sv], g_Plo[(size_t)BHv*Sv*Sv];

// bf16 hi/lo split weights
#define N_WU  ((size_t)Lv*3*Tv*Dv)
#define N_WO  ((size_t)Lv*Dv*Tv)
#define N_F1  ((size_t)Lv*FFv*Dv)
#define N_F2  ((size_t)Lv*Dv*FFv)
#define N_EMB ((size_t)Vv*Dv)
#define OFF_WU  0ull
#define OFF_WO  (OFF_WU + N_WU)
#define OFF_F1  (OFF_WO + N_WO)
#define OFF_F2  (OFF_F1 + N_F1)
#define OFF_EMB (OFF_F2 + N_F2)
#define N_WTOT  (OFF_EMB + N_EMB)
__device__ __nv_bfloat16 g_Whi[N_WTOT];
__device__ __nv_bfloat16 g_Wlo[N_WTOT];
// split activations: A ping (LN out / attn out), B pong (F1 out -> F2 in).
__device__ __nv_bfloat16 g_Ahi[(size_t)BS*Dv],  g_Alo[(size_t)BS*Dv];
__device__ __nv_bfloat16 g_Bhi[(size_t)BS*FFv], g_Blo[(size_t)BS*FFv];

// fp32 C-output selectors (device-side; avoids host symbol API)
#define SEL_U  0
#define SEL_X  1
__device__ __forceinline__ float* sel_buf(int s, float* ext) {
    switch (s) {
        case SEL_U: return g_U;
        case SEL_X: return g_X;
    }
    return ext;
}

// ---------------- reductions ----------------
__device__ __forceinline__ float block_sum(float v, float* red) {
    #pragma unroll
    for (int o = 16; o; o >>= 1) v += __shfl_xor_sync(0xffffffffu, v, o);
    if ((threadIdx.x & 31) == 0) red[threadIdx.x >> 5] = v;
    __syncthreads();
    float t = 0.f;
    #pragma unroll
    for (int w = 0; w < 8; w++) t += red[w];
    __syncthreads();
    return t;
}
__device__ __forceinline__ float block_max(float v, float* red) {
    #pragma unroll
    for (int o = 16; o; o >>= 1) v = fmaxf(v, __shfl_xor_sync(0xffffffffu, v, o));
    if ((threadIdx.x & 31) == 0) red[threadIdx.x >> 5] = v;
    __syncthreads();
    float t = -1e30f;
    #pragma unroll
    for (int w = 0; w < 8; w++) t = fmaxf(t, red[w]);
    __syncthreads();
    return t;
}

// ---------------- hi/lo split ----------------
__device__ __forceinline__ void split2(float x, float y, uint32_t& hi, uint32_t& lo) {
    __nv_bfloat16 hx = __float2bfloat16(x);
    __nv_bfloat16 hy = __float2bfloat16(y);
    __nv_bfloat16 lx = __float2bfloat16(x - __bfloat162float(hx));
    __nv_bfloat16 ly = __float2bfloat16(y - __bfloat162float(hy));
    __nv_bfloat162 h2 = __nv_bfloat162(hx, hy);
    __nv_bfloat162 l2 = __nv_bfloat162(lx, ly);
    hi = *(uint32_t*)&h2;
    lo = *(uint32_t*)&l2;
}
__global__ void __launch_bounds__(256) conv_w_k(const float* __restrict__ src, size_t off, int n4) {
    int i = blockIdx.x * 256 + threadIdx.x;
    if (i >= n4) return;
    float4 v = ((const float4*)src)[i];
    uint32_t h0, l0, h1, l1;
    split2(v.x, v.y, h0, l0);
    split2(v.z, v.w, h1, l1);
    uint32_t* dh = (uint32_t*)(g_Whi + off);
    uint32_t* dl = (uint32_t*)(g_Wlo + off);
    dh[2*i] = h0; dh[2*i+1] = h1;
    dl[2*i] = l0; dl[2*i+1] = l1;
}

// ---------------- embedding gather ----------------
__global__ void __launch_bounds__(256) embed_k(const int* __restrict__ ids,
                                               const float* __restrict__ emb) {
    int r = blockIdx.x;
    int id = ids[r];
    float4 v = ((const float4*)(emb + (size_t)id * Dv))[threadIdx.x];
    ((float4*)(g_X + (size_t)r * Dv))[threadIdx.x] = v;
}

// ---------------- layernorm fused with hi/lo split -> g_Ahi/g_Alo ----------------
__global__ void __launch_bounds__(256) layernorm_split_k(const float* __restrict__ w,
                                                         const float* __restrict__ b) {
    __shared__ float red[8];
    int r = blockIdx.x, tid = threadIdx.x;
    float4 v = ((const float4*)(g_X + (size_t)r * Dv))[tid];
    float s = block_sum(v.x + v.y + v.z + v.w, red);
    float mu = s * (1.0f / Dv);
    float dx = v.x - mu, dy = v.y - mu, dz = v.z - mu, dw = v.w - mu;
    float sq = block_sum(dx*dx + dy*dy + dz*dz + dw*dw, red);
    float inv = rsqrtf(sq * (1.0f / Dv) + 1e-5f);
    float4 wv = ((const float4*)w)[tid];
    float4 bv = ((const float4*)b)[tid];
    float ox = dx * inv * wv.x + bv.x;
    float oy = dy * inv * wv.y + bv.y;
    float oz = dz * inv * wv.z + bv.z;
    float ow = dw * inv * wv.w + bv.w;
    uint32_t h0, l0, h1, l1;
    split2(ox, oy, h0, l0);
    split2(oz, ow, h1, l1);
    size_t base = ((size_t)r * Dv) / 2 + tid * 2;
    ((uint32_t*)g_Ahi)[base] = h0; ((uint32_t*)g_Ahi)[base + 1] = h1;
    ((uint32_t*)g_Alo)[base] = l0; ((uint32_t*)g_Alo)[base + 1] = l1;
}

// =====================================================================
// bf16 split-precision MMA GEMM: C(MxN) = A(MxK)*B(NxK)^T
// CTA tile 128x64 (8 warps, 4x2, warp tile 32x32) -> fine-grained tiles
// kill wave quantization (384->768 etc: 86-96% wave fill vs 65%).
// All LDSM hoisted to stage start (no LDSM->MMA dependency stall).
// asel: 0 = A from g_Ahi/g_Alo, 1 = A from g_Bhi/g_Blo.
// OSPLIT: epilogue writes bf16 hi/lo into g_Bhi/g_Blo.
// =====================================================================
template<bool BIAS, bool GELU, bool RES, bool OSPLIT>
__global__ void __launch_bounds__(256, 2) gemm_mma(size_t wOff,
                                                   const float* __restrict__ bias,
                                                   float* __restrict__ extC,
                                                   int csel, int asel,
                                                   int M, int N, int K) {
    __shared__ __align__(16) uint8_t sA[2][2][6144];  // [stage][hi/lo][128 rows * 48B]
    __shared__ __align__(16) uint8_t sB[2][2][3072];  // [stage][hi/lo][64 rows * 48B]

    int tid = threadIdx.x, lane = tid & 31, wid = tid >> 5;
    int warp_m = wid >> 1, warp_n = wid & 1;          // 4 x 2
    int m0 = blockIdx.x * 128, n0 = blockIdx.y * 64;
    float* C = OSPLIT ? nullptr : ((csel >= 0) ? sel_buf(csel, nullptr) : extC);
    const __nv_bfloat16* Ahi = asel ? g_Bhi : g_Ahi;
    const __nv_bfloat16* Alo = asel ? g_Blo : g_Alo;

    // A loader: 256 threads, row = tid>>1 (0..127), 16B half h = tid&1
    int r = tid >> 1, h = tid & 1;
    const __nv_bfloat16* gAh = Ahi + (size_t)(m0 + r) * K + h * 8;
    const __nv_bfloat16* gAl = Alo + (size_t)(m0 + r) * K + h * 8;
    // B loader: threads 0-127 -> hi, 128-255 -> lo; row = (tid&127)>>1
    int rb = (tid & 127) >> 1, hb = tid & 1;
    const __nv_bfloat16* gB = (tid < 128 ? g_Whi : g_Wlo) + wOff + (size_t)(n0 + rb) * K + hb * 8;

    uint32_t aS = smem_to_u32(&sA[0][0][0]);
    uint32_t bS = smem_to_u32(&sB[0][0][0]);
    uint32_t dA = aS + r * 48 + h * 16;
    uint32_t dB = bS + (tid >= 128 ? 3072u : 0u) + rb * 48 + hb * 16;

    float acc[2][4][4];
    #pragma unroll
    for (int mi = 0; mi < 2; mi++)
        #pragma unroll
        for (int nj = 0; nj < 4; nj++)
            #pragma unroll
            for (int q = 0; q < 4; q++) acc[mi][nj][q] = 0.f;

    const int NST = K >> 4;
    // prologue: stages 0,1
    {
        CP_ASYNC16(dA,        gAh);
        CP_ASYNC16(dA + 6144, gAl);
        CP_ASYNC16(dB,        gB);
        CP_COMMIT();
        CP_ASYNC16(dA + 12288,        gAh + 16);
        CP_ASYNC16(dA + 12288 + 6144, gAl + 16);
        CP_ASYNC16(dB + 6144,         gB + 16);
        CP_COMMIT();
    }

    int a_row = lane & 15, a_chunk = lane >> 4;
    int b_row = (lane & 7) | ((lane >> 4) << 3);
    int b_chunk = (lane >> 3) & 1;
    uint32_t aAddr0 = aS + (uint32_t)((warp_m * 32 + a_row) * 48 + a_chunk * 16);
    uint32_t bAddr0 = bS + (uint32_t)((warp_n * 32 + b_row) * 48 + b_chunk * 16);

    for (int st = 0; st < NST; st++) {
        int s = st & 1;
        if (st + 1 < NST) { CP_WAIT1(); } else { CP_WAIT0(); }
        __syncthreads();

        uint32_t aBase = aAddr0 + (uint32_t)s * 12288u;
        uint32_t bBase = bAddr0 + (uint32_t)s * 6144u;

        // hoist ALL fragment loads for this stage
        uint32_t ah[2][4], al[2][4], bh[2][4], bl[2][4];
        #pragma unroll
        for (int mi = 0; mi < 2; mi++) {
            LDSM_X4(ah[mi][0], ah[mi][1], ah[mi][2], ah[mi][3], aBase + mi * 768u);
            LDSM_X4(al[mi][0], al[mi][1], al[mi][2], al[mi][3], aBase + 6144u + mi * 768u);
        }
        #pragma unroll
        for (int p = 0; p < 2; p++) {
            LDSM_X4(bh[p][0], bh[p][1], bh[p][2], bh[p][3], bBase + p * 768u);
            LDSM_X4(bl[p][0], bl[p][1], bl[p][2], bl[p][3], bBase + 3072u + p * 768u);
        }

        #pragma unroll
        for (int p = 0; p < 2; p++)
            #pragma unroll
            for (int mi = 0; mi < 2; mi++) {
                MMA_BF16(acc[mi][2*p],   ah[mi][0], ah[mi][1], ah[mi][2], ah[mi][3], bh[p][0], bh[p][1]);
                MMA_BF16(acc[mi][2*p+1], ah[mi][0], ah[mi][1], ah[mi][2], ah[mi][3], bh[p][2], bh[p][3]);
                MMA_BF16(acc[mi][2*p],   al[mi][0], al[mi][1], al[mi][2], al[mi][3], bh[p][0], bh[p][1]);
                MMA_BF16(acc[mi][2*p+1], al[mi][0], al[mi][1], al[mi][2], al[mi][3], bh[p][2], bh[p][3]);
                MMA_BF16(acc[mi][2*p],   ah[mi][0], ah[mi][1], ah[mi][2], ah[mi][3], bl[p][0], bl[p][1]);
                MMA_BF16(acc[mi][2*p+1], ah[mi][0], ah[mi][1], ah[mi][2], ah[mi][3], bl[p][2], bl[p][3]);
            }

        __syncthreads();
        if (st + 2 < NST) {
            int k0 = (st + 2) << 4;
            uint32_t dsA = (uint32_t)s * 12288u;
            uint32_t dsB = (uint32_t)s * 6144u;
            CP_ASYNC16(dA + dsA,        gAh + k0);
            CP_ASYNC16(dA + dsA + 6144, gAl + k0);
            CP_ASYNC16(dB + dsB,        gB + k0);
            CP_COMMIT();
        }
    }

    int crow = lane >> 2, ccol = (lane & 3) * 2;
    #pragma unroll
    for (int mi = 0; mi < 2; mi++) {
        int m = m0 + warp_m * 32 + mi * 16 + crow;
        #pragma unroll
        for (int nj = 0; nj < 4; nj++) {
            int n = n0 + warp_n * 32 + nj * 8 + ccol;
            float v0 = acc[mi][nj][0], v1 = acc[mi][nj][1];
            float v2 = acc[mi][nj][2], v3 = acc[mi][nj][3];
            if (BIAS) {
                float b0 = bias[n], b1 = bias[n + 1];
                v0 += b0; v1 += b1; v2 += b0; v3 += b1;
            }
            if (GELU) {
                v0 = 0.5f * v0 * (1.0f + erff(v0 * 0.70710678118654752f));
                v1 = 0.5f * v1 * (1.0f + erff(v1 * 0.70710678118654752f));
                v2 = 0.5f * v2 * (1.0f + erff(v2 * 0.70710678118654752f));
                v3 = 0.5f * v3 * (1.0f + erff(v3 * 0.70710678118654752f));
            }
            size_t o0 = (size_t)m * N + n;
            size_t o1 = (size_t)(m + 8) * N + n;
            if (OSPLIT) {
                uint32_t hi, lo;
                split2(v0, v1, hi, lo);
                ((uint32_t*)g_Bhi)[o0 >> 1] = hi;
                ((uint32_t*)g_Blo)[o0 >> 1] = lo;
                split2(v2, v3, hi, lo);
                ((uint32_t*)g_Bhi)[o1 >> 1] = hi;
                ((uint32_t*)g_Blo)[o1 >> 1] = lo;
            } else {
                if (RES) {
                    float2 r0 = *(float2*)&C[o0];
                    float2 r1 = *(float2*)&C[o1];
                    v0 += r0.x; v1 += r0.y; v2 += r1.x; v3 += r1.y;
                }
                *(float2*)&C[o0] = make_float2(v0, v1);
                *(float2*)&C[o1] = make_float2(v2, v3);
            }
        }
    }
}

// ---------------- qkv split + rope -> bf16 hi/lo ----------------
__global__ void __launch_bounds__(256) qkv_rope_k() {
    int idx = blockIdx.x * 256 + threadIdx.x;      // bh*65536 + s*64 + d
    int d  = idx & 63;
    int s  = (idx >> 6) & (Sv - 1);
    int bh = idx >> 16;
    int b = bh >> 4, h = bh & 15;
    const float* u = g_U + ((size_t)(b * Sv + s)) * (3 * Tv) + h * 64;
    float uq = u[d], uk = u[Tv + d], uv = u[2 * Tv + d];
    int i  = d & 31;
    int d2 = (d < 32) ? d + 32 : d - 32;
    float uq2 = u[d2], uk2 = u[Tv + d2];
    float invf = powf(10000.0f, -(float)i / 32.0f);
    float ang = (float)s * invf;
    float c, sn;
    sincosf(ang, &sn, &c);
    float sgn = (d < 32) ? -1.0f : 1.0f;
    float q = uq * c + sgn * uq2 * sn;
    float k = uk * c + sgn * uk2 * sn;
    __nv_bfloat16 qh = __float2bfloat16(q);
    __nv_bfloat16 kh = __float2bfloat16(k);
    __nv_bfloat16 vh = __float2bfloat16(uv);
    g_Qh[idx] = qh; g_Ql[idx] = __float2bfloat16(q - __bfloat162float(qh));
    g_Kh[idx] = kh; g_Kl[idx] = __float2bfloat16(k - __bfloat162float(kh));
    g_Vh[idx] = vh; g_Vl[idx] = __float2bfloat16(uv - __bfloat162float(vh));
}

// ---------------- V transpose: [bh][s][d] -> [bh][d][s] ----------------
__global__ void __launch_bounds__(256) vT_k() {
    __shared__ uint16_t t[2][64][65];
    int bh = blockIdx.y, s0 = blockIdx.x * 64;
    size_t base = (size_t)bh * Sv * HDv;
    const uint16_t* Vh = (const uint16_t*)g_Vh;
    const uint16_t* Vl = (const uint16_t*)g_Vl;
    uint16_t* Th = (uint16_t*)g_VTh;
    uint16_t* Tl = (uint16_t*)g_VTl;
    #pragma unroll
    for (int i = 0; i < 16; i++) {
        int f = threadIdx.x + i * 256;
        int sr = f >> 6, dc = f & 63;
        size_t g = base + (size_t)(s0 + sr) * HDv + dc;
        t[0][sr][dc] = Vh[g];
        t[1][sr][dc] = Vl[g];
    }
    __syncthreads();
    #pragma unroll
    for (int i = 0; i < 16; i++) {
        int f = threadIdx.x + i * 256;
        int d = f >> 6, ss = f & 63;
        size_t g = base + (size_t)d * Sv + s0 + ss;
        Th[g] = t[0][ss][d];
        Tl[g] = t[1][ss][d];
    }
}

// =====================================================================
// attention scores (tensorized): P = Q K^T / 8, 64x64 tiles, causal skip
// =====================================================================
__global__ void __launch_bounds__(128) attn_scores_mma() {
    int bh = blockIdx.z;
    int q0 = blockIdx.y * 64, k0 = blockIdx.x * 64;
    if (k0 > q0 + 63) return;
    __shared__ __align__(16) uint8_t sQ[2][9216];   // [hi/lo][64 rows * 144B]
    __shared__ __align__(16) uint8_t sK[2][9216];

    int tid = threadIdx.x, lane = tid & 31, w = tid >> 5;
    size_t base = (size_t)bh * Sv * HDv;
    uint32_t qS = smem_to_u32(&sQ[0][0]);
    uint32_t kS = smem_to_u32(&sK[0][0]);

    #pragma unroll
    for (int i = 0; i < 4; i++) {
        int f = tid + i * 128;
        int row = f >> 3, seg = f & 7;
        uint32_t so = (uint32_t)(row * 144 + seg * 16);
        size_t gq = base + (size_t)(q0 + row) * HDv + seg * 8;
        size_t gk = base + (size_t)(k0 + row) * HDv + seg * 8;
        CP_ASYNC16(qS + so,        g_Qh + gq);
        CP_ASYNC16(qS + 9216 + so, g_Ql + gq);
        CP_ASYNC16(kS + so,        g_Kh + gk);
        CP_ASYNC16(kS + 9216 + so, g_Kl + gk);
    }
    CP_COMMIT(); CP_WAIT0();
    __syncthreads();

    float acc[8][4];
    #pragma unroll
    for (int nj = 0; nj < 8; nj++)
        #pragma unroll
        for (int q = 0; q < 4; q++) acc[nj][q] = 0.f;

    int a_row = lane & 15, a_chunk = lane >> 4;
    int b_row = (lane & 7) | ((lane >> 4) << 3);
    int b_chunk = (lane >> 3) & 1;
    uint32_t aB = qS + (uint32_t)((w * 16 + a_row) * 144 + a_chunk * 16);
    uint32_t bB = kS + (uint32_t)(b_row * 144 + b_chunk * 16);

    #pragma unroll
    for (int ks = 0; ks < 4; ks++) {
        uint32_t ah[4], al[4];
        LDSM_X4(ah[0], ah[1], ah[2], ah[3], aB + ks * 32u);
        LDSM_X4(al[0], al[1], al[2], al[3], aB + 9216u + ks * 32u);
        #pragma unroll
        for (int g = 0; g < 4; g++) {
            uint32_t b0, b1, b2, b3;
            LDSM_X4(b0, b1, b2, b3, bB + g * 2304u + ks * 32u);
            MMA_BF16(acc[2*g],   ah[0], ah[1], ah[2], ah[3], b0, b1);
            MMA_BF16(acc[2*g+1], ah[0], ah[1], ah[2], ah[3], b2, b3);
            MMA_BF16(acc[2*g],   al[0], al[1], al[2], al[3], b0, b1);
            MMA_BF16(acc[2*g+1], al[0], al[1], al[2], al[3], b2, b3);
            LDSM_X4(b0, b1, b2, b3, bB + 9216u + g * 2304u + ks * 32u);
            MMA_BF16(acc[2*g],   ah[0], ah[1], ah[2], ah[3], b0, b1);
            MMA_BF16(acc[2*g+1], ah[0], ah[1], ah[2], ah[3], b2, b3);
        }
    }

    float* out = g_P + (size_t)bh * Sv * Sv;
    int crow = lane >> 2, ccol = (lane & 3) * 2;
    int qq = q0 + w * 16 + crow;
    #pragma unroll
    for (int nj = 0; nj < 8; nj++) {
        int kk = k0 + nj * 8 + ccol;
        out[(size_t)qq * Sv + kk]       = acc[nj][0] * 0.125f;
        out[(size_t)qq * Sv + kk + 1]   = acc[nj][1] * 0.125f;
        out[(size_t)(qq+8) * Sv + kk]   = acc[nj][2] * 0.125f;
        out[(size_t)(qq+8) * Sv + kk+1] = acc[nj][3] * 0.125f;
    }
}

// ---------------- causal softmax: fp32 scores -> bf16 hi/lo probs ----------------
__global__ void __launch_bounds__(256) attn_softmax_k() {
    __shared__ float red[8];
    int idx = blockIdx.x;            // bh*S + q
    int q = idx & (Sv - 1);
    float* row = g_P + (size_t)idx * Sv;
    int len = q + 1;
    int kup = ((q >> 6) + 1) << 6;
    int tid = threadIdx.x;
    float mx = -1e30f;
    for (int k = tid; k < len; k += 256) mx = fmaxf(mx, row[k]);
    mx = block_max(mx, red);
    float sum = 0.f;
    for (int k = tid; k < len; k += 256) {
        float e = expf(row[k] - mx);
        row[k] = e;
        sum += e;
    }
    sum = block_sum(sum, red);
    float inv = 1.0f / sum;
    for (int k = tid; k < kup; k += 256) {
        float p = (k < len) ? row[k] * inv : 0.0f;
        __nv_bfloat16 ph = __float2bfloat16(p);
        g_Phi[(size_t)idx * Sv + k] = ph;
        g_Plo[(size_t)idx * Sv + k] = __float2bfloat16(p - __bfloat162float(ph));
    }
}

// =====================================================================
// PV (tensorized): AO[q][d] = P[q][k] * VT[d][k], causal K-bound.
// =====================================================================
__global__ void __launch_bounds__(128) attn_pv_mma() {
    int bh = blockIdx.y;
    int q0 = blockIdx.x * 64;
    __shared__ __align__(16) uint8_t sP[2][9216];
    __shared__ __align__(16) uint8_t sV[2][9216];

    int tid = threadIdx.x, lane = tid & 31, w = tid >> 5;
    size_t pBase = (size_t)(bh * Sv) * Sv;
    size_t vBase = (size_t)bh * Sv * HDv;
    uint32_t pS = smem_to_u32(&sP[0][0]);
    uint32_t vS = smem_to_u32(&sV[0][0]);

    float acc[8][4];
    #pragma unroll
    for (int nj = 0; nj < 8; nj++)
        #pragma unroll
        for (int q = 0; q < 4; q++) acc[nj][q] = 0.f;

    int a_row = lane & 15, a_chunk = lane >> 4;
    int b_row = (lane & 7) | ((lane >> 4) << 3);
    int b_chunk = (lane >> 3) & 1;
    uint32_t aB = pS + (uint32_t)((w * 16 + a_row) * 144 + a_chunk * 16);
    uint32_t bB = vS + (uint32_t)(b_row * 144 + b_chunk * 16);

    int kmax = q0 + 64;
    for (int kc = 0; kc < kmax; kc += 64) {
        #pragma unroll
        for (int i = 0; i < 4; i++) {
            int f = tid + i * 128;
            int row = f >> 3, seg = f & 7;
            uint32_t so = (uint32_t)(row * 144 + seg * 16);
            size_t gp = pBase + (size_t)(q0 + row) * Sv + kc + seg * 8;
            size_t gv = vBase + (size_t)row * Sv + kc + seg * 8;
            CP_ASYNC16(pS + so,        g_Phi + gp);
            CP_ASYNC16(pS + 9216 + so, g_Plo + gp);
            CP_ASYNC16(vS + so,        g_VTh + gv);
            CP_ASYNC16(vS + 9216 + so, g_VTl + gv);
        }
        CP_COMMIT(); CP_WAIT0();
        __syncthreads();

        #pragma unroll
        for (int ks = 0; ks < 4; ks++) {
            uint32_t ah[4], al[4];
            LDSM_X4(ah[0], ah[1], ah[2], ah[3], aB + ks * 32u);
            LDSM_X4(al[0], al[1], al[2], al[3], aB + 9216u + ks * 32u);
            #pragma unroll
            for (int g = 0; g < 4; g++) {
                uint32_t b0, b1, b2, b3;
                LDSM_X4(b0, b1, b2, b3, bB + g * 2304u + ks * 32u);
                MMA_BF16(acc[2*g],   ah[0], ah[1], ah[2], ah[3], b0, b1);
                MMA_BF16(acc[2*g+1], ah[0], ah[1], ah[2], ah[3], b2, b3);
                MMA_BF16(acc[2*g],   al[0], al[1], al[2], al[3], b0, b1);
                MMA_BF16(acc[2*g+1], al[0], al[1], al[2], al[3], b2, b3);
                LDSM_X4(b0, b1, b2, b3, bB + 9216u + g * 2304u + ks * 32u);
                MMA_BF16(acc[2*g],   ah[0], ah[1], ah[2], ah[3], b0, b1);
                MMA_BF16(acc[2*g+1], ah[0], ah[1], ah[2], ah[3], b2, b3);
            }
        }
        __syncthreads();
    }

    int b = bh >> 4, h = bh & 15;
    int crow = lane >> 2, ccol = (lane & 3) * 2;
    int q = q0 + w * 16 + crow;
    #pragma unroll
    for (int nj = 0; nj < 8; nj++) {
        int d = nj * 8 + ccol;
        uint32_t hi, lo;
        split2(acc[nj][0], acc[nj][1], hi, lo);
        size_t o0 = (size_t)(b * Sv + q) * Tv + h * 64 + d;
        *(uint32_t*)&g_Ahi[o0] = hi;
        *(uint32_t*)&g_Alo[o0] = lo;
        split2(acc[nj][2], acc[nj][3], hi, lo);
        size_t o1 = (size_t)(b * Sv + q + 8) * Tv + h * 64 + d;
        *(uint32_t*)&g_Ahi[o1] = hi;
        *(uint32_t*)&g_Alo[o1] = lo;
    }
}

// ---------------- launch (kernel launches ONLY) ----------------
extern "C" void kernel_launch(void* const* d_in, const int* in_sizes, int n_in,
                              void* d_out, int out_size) {
    const int*   ids = (const int*)  d_in[0];
    const float* emb = (const float*)d_in[1];
    const float* Wu  = (const float*)d_in[2];
    const float* Wo  = (const float*)d_in[3];
    const float* n1w = (const float*)d_in[4];
    const float* n1b = (const float*)d_in[5];
    const float* n2w = (const float*)d_in[6];
    const float* n2b = (const float*)d_in[7];
    const float* f1w = (const float*)d_in[8];
    const float* f1b = (const float*)d_in[9];
    const float* f2w = (const float*)d_in[10];
    const float* f2b = (const float*)d_in[11];
    const float* fnw = (const float*)d_in[12];
    const float* fnb = (const float*)d_in[13];
    float* out = (float*)d_out;

    // front-load so the QKV gemm is launch #4 (ncu capture window)
    embed_k<<<BS, 256>>>(ids, emb);
    conv_w_k<<<(int)((N_WU/4  + 255) / 256), 256>>>(Wu,  OFF_WU,  (int)(N_WU/4));
    layernorm_split_k<<<BS, 256>>>(n1w, n1b);
    gemm_mma<false, false, false, false><<<dim3(BS / 128, 3 * Tv / 64), 256>>>(
        OFF_WU, nullptr, nullptr, SEL_U, 0, BS, 3 * Tv, Dv);
    conv_w_k<<<(int)((N_WO/4  + 255) / 256), 256>>>(Wo,  OFF_WO,  (int)(N_WO/4));
    conv_w_k<<<(int)((N_F1/4  + 255) / 256), 256>>>(f1w, OFF_F1,  (int)(N_F1/4));
    conv_w_k<<<(int)((N_F2/4  + 255) / 256), 256>>>(f2w, OFF_F2,  (int)(N_F2/4));
    conv_w_k<<<(int)((N_EMB/4 + 255) / 256), 256>>>(emb, OFF_EMB, (int)(N_EMB/4));

    for (int l = 0; l < Lv; l++) {
        if (l > 0) {
            layernorm_split_k<<<BS, 256>>>(n1w + l * Dv, n1b + l * Dv);
            gemm_mma<false, false, false, false><<<dim3(BS / 128, 3 * Tv / 64), 256>>>(
                OFF_WU + (size_t)l * 3 * Tv * Dv, nullptr, nullptr, SEL_U, 0, BS, 3 * Tv, Dv);
        }
        qkv_rope_k<<<(BHv * Sv * HDv) / 256, 256>>>();
        vT_k<<<dim3(Sv / 64, BHv), 256>>>();
        attn_scores_mma<<<dim3(Sv / 64, Sv / 64, BHv), 128>>>();
        attn_softmax_k<<<BHv * Sv, 256>>>();
        attn_pv_mma<<<dim3(Sv / 64, BHv), 128>>>();
        gemm_mma<false, false, true, false><<<dim3(BS / 128, Dv / 64), 256>>>(
            OFF_WO + (size_t)l * Dv * Tv, nullptr, nullptr, SEL_X, 0, BS, Dv, Tv);

        layernorm_split_k<<<BS, 256>>>(n2w + l * Dv, n2b + l * Dv);
        gemm_mma<true, true, false, true><<<dim3(BS / 128, FFv / 64), 256>>>(
            OFF_F1 + (size_t)l * FFv * Dv, f1b + (size_t)l * FFv, nullptr, -1, 0, BS, FFv, Dv);
        gemm_mma<true, false, true, false><<<dim3(BS / 128, Dv / 64), 256>>>(
            OFF_F2 + (size_t)l * Dv * FFv, f2b + (size_t)l * Dv, nullptr, SEL_X, 1, BS, Dv, FFv);
    }

    // ---- final LN + tied-embedding logits ----
    layernorm_split_k<<<BS, 256>>>(fnw, fnb);
    gemm_mma<false, false, false, false><<<dim3(BS / 128, Vv / 64), 256>>>(
        OFF_EMB, nullptr, out, -1, 0, BS, Vv, Dv);
}

// round 13
// speedup vs baseline: 1.0202x; 1.0202x over previous
#include <cuda_runtime.h>
#include <cuda_bf16.h>
#include <math.h>
#include <cstdint>

// ---------------- problem dims ----------------
#define Bv   2
#define Sv   1024
#define Dv   1024
#define Hh   16
#define HDv  64
#define Tv   1024
#define FFv  4096
#define Lv   8
#define Vv   32000
#define BS   (Bv*Sv)     // 2048
#define BHv  (Bv*Hh)     // 32

// ============ PTX helpers (baseline PTX only: sm_80-class features) ============
__device__ __forceinline__ uint32_t smem_to_u32(const void* p) {
    uint32_t a;
    asm("{ .reg .u64 t; cvta.to.shared.u64 t, %1; cvt.u32.u64 %0, t; }" : "=r"(a) : "l"(p));
    return a;
}
#define CP_ASYNC16(dst, src) \
    asm volatile("cp.async.cg.shared.global [%0], [%1], 16;" :: "r"(dst), "l"(src))
#define CP_COMMIT() asm volatile("cp.async.commit_group;" ::: "memory")
#define CP_WAIT1()  asm volatile("cp.async.wait_group 1;" ::: "memory")
#define CP_WAIT0()  asm volatile("cp.async.wait_group 0;" ::: "memory")
#define LDSM_X4(R0, R1, R2, R3, ADDR) \
    asm volatile("ldmatrix.sync.aligned.m8n8.x4.shared.b16 {%0,%1,%2,%3}, [%4];" \
        : "=r"(R0), "=r"(R1), "=r"(R2), "=r"(R3) : "r"(ADDR))
#define MMA_BF16(D, A0, A1, A2, A3, B0, B1) \
    asm volatile("mma.sync.aligned.m16n8k16.row.col.f32.bf16.bf16.f32 " \
        "{%0,%1,%2,%3},{%4,%5,%6,%7},{%8,%9},{%0,%1,%2,%3};" \
        : "+f"((D)[0]), "+f"((D)[1]), "+f"((D)[2]), "+f"((D)[3]) \
        : "r"(A0), "r"(A1), "r"(A2), "r"(A3), "r"(B0), "r"(B1))

// ---------------- scratch (device globals; no allocations, no host API) ----------------
__device__ float g_X [BS*Dv];
__device__ float g_U [BS*3*Tv];
__device__ float g_P [(size_t)BHv*Sv*Sv];           // fp32 scores

// attention bf16 hi/lo buffers
__device__ __nv_bfloat16 g_Qh[BHv*Sv*HDv], g_Ql[BHv*Sv*HDv];
__device__ __nv_bfloat16 g_Kh[BHv*Sv*HDv], g_Kl[BHv*Sv*HDv];
__device__ __nv_bfloat16 g_Vh[BHv*Sv*HDv], g_Vl[BHv*Sv*HDv];
__device__ __nv_bfloat16 g_VTh[BHv*Sv*HDv], g_VTl[BHv*Sv*HDv];   // [bh][d][s]
__device__ __nv_bfloat16 g_Phi[(size_t)BHv*Sv*Sv], g_Plo[(size_t)BHv*Sv*Sv];

// bf16 hi/lo split weights
#define N_WU  ((size_t)Lv*3*Tv*Dv)
#define N_WO  ((size_t)Lv*Dv*Tv)
#define N_F1  ((size_t)Lv*FFv*Dv)
#define N_F2  ((size_t)Lv*Dv*FFv)
#define N_EMB ((size_t)Vv*Dv)
#define OFF_WU  0ull
#define OFF_WO  (OFF_WU + N_WU)
#define OFF_F1  (OFF_WO + N_WO)
#define OFF_F2  (OFF_F1 + N_F1)
#define OFF_EMB (OFF_F2 + N_F2)
#define N_WTOT  (OFF_EMB + N_EMB)
__device__ __nv_bfloat16 g_Whi[N_WTOT];
__device__ __nv_bfloat16 g_Wlo[N_WTOT];
// split activations: A ping (LN out / attn out), B pong (F1 out -> F2 in).
__device__ __nv_bfloat16 g_Ahi[(size_t)BS*Dv],  g_Alo[(size_t)BS*Dv];
__device__ __nv_bfloat16 g_Bhi[(size_t)BS*FFv], g_Blo[(size_t)BS*FFv];

// fp32 C-output selectors (device-side; avoids host symbol API)
#define SEL_U  0
#define SEL_X  1
__device__ __forceinline__ float* sel_buf(int s, float* ext) {
    switch (s) {
        case SEL_U: return g_U;
        case SEL_X: return g_X;
    }
    return ext;
}

// ---------------- reductions ----------------
__device__ __forceinline__ float block_sum(float v, float* red) {
    #pragma unroll
    for (int o = 16; o; o >>= 1) v += __shfl_xor_sync(0xffffffffu, v, o);
    if ((threadIdx.x & 31) == 0) red[threadIdx.x >> 5] = v;
    __syncthreads();
    float t = 0.f;
    #pragma unroll
    for (int w = 0; w < 8; w++) t += red[w];
    __syncthreads();
    return t;
}
__device__ __forceinline__ float block_max(float v, float* red) {
    #pragma unroll
    for (int o = 16; o; o >>= 1) v = fmaxf(v, __shfl_xor_sync(0xffffffffu, v, o));
    if ((threadIdx.x & 31) == 0) red[threadIdx.x >> 5] = v;
    __syncthreads();
    float t = -1e30f;
    #pragma unroll
    for (int w = 0; w < 8; w++) t = fmaxf(t, red[w]);
    __syncthreads();
    return t;
}

// ---------------- hi/lo split ----------------
__device__ __forceinline__ void split2(float x, float y, uint32_t& hi, uint32_t& lo) {
    __nv_bfloat16 hx = __float2bfloat16(x);
    __nv_bfloat16 hy = __float2bfloat16(y);
    __nv_bfloat16 lx = __float2bfloat16(x - __bfloat162float(hx));
    __nv_bfloat16 ly = __float2bfloat16(y - __bfloat162float(hy));
    __nv_bfloat162 h2 = __nv_bfloat162(hx, hy);
    __nv_bfloat162 l2 = __nv_bfloat162(lx, ly);
    hi = *(uint32_t*)&h2;
    lo = *(uint32_t*)&l2;
}
__global__ void __launch_bounds__(256) conv_w_k(const float* __restrict__ src, size_t off, int n4) {
    int i = blockIdx.x * 256 + threadIdx.x;
    if (i >= n4) return;
    float4 v = ((const float4*)src)[i];
    uint32_t h0, l0, h1, l1;
    split2(v.x, v.y, h0, l0);
    split2(v.z, v.w, h1, l1);
    uint32_t* dh = (uint32_t*)(g_Whi + off);
    uint32_t* dl = (uint32_t*)(g_Wlo + off);
    dh[2*i] = h0; dh[2*i+1] = h1;
    dl[2*i] = l0; dl[2*i+1] = l1;
}

// ---------------- embedding gather ----------------
__global__ void __launch_bounds__(256) embed_k(const int* __restrict__ ids,
                                               const float* __restrict__ emb) {
    int r = blockIdx.x;
    int id = ids[r];
    float4 v = ((const float4*)(emb + (size_t)id * Dv))[threadIdx.x];
    ((float4*)(g_X + (size_t)r * Dv))[threadIdx.x] = v;
}

// ---------------- layernorm fused with hi/lo split -> g_Ahi/g_Alo ----------------
__global__ void __launch_bounds__(256) layernorm_split_k(const float* __restrict__ w,
                                                         const float* __restrict__ b) {
    __shared__ float red[8];
    int r = blockIdx.x, tid = threadIdx.x;
    float4 v = ((const float4*)(g_X + (size_t)r * Dv))[tid];
    float s = block_sum(v.x + v.y + v.z + v.w, red);
    float mu = s * (1.0f / Dv);
    float dx = v.x - mu, dy = v.y - mu, dz = v.z - mu, dw = v.w - mu;
    float sq = block_sum(dx*dx + dy*dy + dz*dz + dw*dw, red);
    float inv = rsqrtf(sq * (1.0f / Dv) + 1e-5f);
    float4 wv = ((const float4*)w)[tid];
    float4 bv = ((const float4*)b)[tid];
    float ox = dx * inv * wv.x + bv.x;
    float oy = dy * inv * wv.y + bv.y;
    float oz = dz * inv * wv.z + bv.z;
    float ow = dw * inv * wv.w + bv.w;
    uint32_t h0, l0, h1, l1;
    split2(ox, oy, h0, l0);
    split2(oz, ow, h1, l1);
    size_t base = ((size_t)r * Dv) / 2 + tid * 2;
    ((uint32_t*)g_Ahi)[base] = h0; ((uint32_t*)g_Ahi)[base + 1] = h1;
    ((uint32_t*)g_Alo)[base] = l0; ((uint32_t*)g_Alo)[base + 1] = l1;
}

// =====================================================================
// bf16 split-precision MMA GEMM: C(MxN) = A(MxK)*B(NxK)^T
// CTA tile 128x64 (8 warps, 4x2, warp tile 32x32).
// __launch_bounds__(256,3): force <=85 regs -> 3 CTAs/SM (24 warps) so
// barrier/LDSM phases of one CTA are covered by the other two.
// asel: 0 = A from g_Ahi/g_Alo, 1 = A from g_Bhi/g_Blo.
// OSPLIT: epilogue writes bf16 hi/lo into g_Bhi/g_Blo.
// =====================================================================
template<bool BIAS, bool GELU, bool RES, bool OSPLIT>
__global__ void __launch_bounds__(256, 3) gemm_mma(size_t wOff,
                                                   const float* __restrict__ bias,
                                                   float* __restrict__ extC,
                                                   int csel, int asel,
                                                   int M, int N, int K) {
    __shared__ __align__(16) uint8_t sA[2][2][6144];  // [stage][hi/lo][128 rows * 48B]
    __shared__ __align__(16) uint8_t sB[2][2][3072];  // [stage][hi/lo][64 rows * 48B]

    int tid = threadIdx.x, lane = tid & 31, wid = tid >> 5;
    int warp_m = wid >> 1, warp_n = wid & 1;          // 4 x 2
    int m0 = blockIdx.x * 128, n0 = blockIdx.y * 64;
    float* C = OSPLIT ? nullptr : ((csel >= 0) ? sel_buf(csel, nullptr) : extC);
    const __nv_bfloat16* Ahi = asel ? g_Bhi : g_Ahi;
    const __nv_bfloat16* Alo = asel ? g_Blo : g_Alo;

    // A loader: 256 threads, row = tid>>1 (0..127), 16B half h = tid&1
    int r = tid >> 1, h = tid & 1;
    const __nv_bfloat16* gAh = Ahi + (size_t)(m0 + r) * K + h * 8;
    const __nv_bfloat16* gAl = Alo + (size_t)(m0 + r) * K + h * 8;
    // B loader: threads 0-127 -> hi, 128-255 -> lo; row = (tid&127)>>1
    int rb = (tid & 127) >> 1, hb = tid & 1;
    const __nv_bfloat16* gB = (tid < 128 ? g_Whi : g_Wlo) + wOff + (size_t)(n0 + rb) * K + hb * 8;

    uint32_t aS = smem_to_u32(&sA[0][0][0]);
    uint32_t bS = smem_to_u32(&sB[0][0][0]);
    uint32_t dA = aS + r * 48 + h * 16;
    uint32_t dB = bS + (tid >= 128 ? 3072u : 0u) + rb * 48 + hb * 16;

    float acc[2][4][4];
    #pragma unroll
    for (int mi = 0; mi < 2; mi++)
        #pragma unroll
        for (int nj = 0; nj < 4; nj++)
            #pragma unroll
            for (int q = 0; q < 4; q++) acc[mi][nj][q] = 0.f;

    const int NST = K >> 4;
    // prologue: stages 0,1
    {
        CP_ASYNC16(dA,        gAh);
        CP_ASYNC16(dA + 6144, gAl);
        CP_ASYNC16(dB,        gB);
        CP_COMMIT();
        CP_ASYNC16(dA + 12288,        gAh + 16);
        CP_ASYNC16(dA + 12288 + 6144, gAl + 16);
        CP_ASYNC16(dB + 6144,         gB + 16);
        CP_COMMIT();
    }

    int a_row = lane & 15, a_chunk = lane >> 4;
    int b_row = (lane & 7) | ((lane >> 4) << 3);
    int b_chunk = (lane >> 3) & 1;
    uint32_t aAddr0 = aS + (uint32_t)((warp_m * 32 + a_row) * 48 + a_chunk * 16);
    uint32_t bAddr0 = bS + (uint32_t)((warp_n * 32 + b_row) * 48 + b_chunk * 16);

    for (int st = 0; st < NST; st++) {
        int s = st & 1;
        if (st + 1 < NST) { CP_WAIT1(); } else { CP_WAIT0(); }
        __syncthreads();

        uint32_t aBase = aAddr0 + (uint32_t)s * 12288u;
        uint32_t bBase = bAddr0 + (uint32_t)s * 6144u;

        // hoist ALL fragment loads for this stage
        uint32_t ah[2][4], al[2][4], bh[2][4], bl[2][4];
        #pragma unroll
        for (int mi = 0; mi < 2; mi++) {
            LDSM_X4(ah[mi][0], ah[mi][1], ah[mi][2], ah[mi][3], aBase + mi * 768u);
            LDSM_X4(al[mi][0], al[mi][1], al[mi][2], al[mi][3], aBase + 6144u + mi * 768u);
        }
        #pragma unroll
        for (int p = 0; p < 2; p++) {
            LDSM_X4(bh[p][0], bh[p][1], bh[p][2], bh[p][3], bBase + p * 768u);
            LDSM_X4(bl[p][0], bl[p][1], bl[p][2], bl[p][3], bBase + 3072u + p * 768u);
        }

        #pragma unroll
        for (int p = 0; p < 2; p++)
            #pragma unroll
            for (int mi = 0; mi < 2; mi++) {
                MMA_BF16(acc[mi][2*p],   ah[mi][0], ah[mi][1], ah[mi][2], ah[mi][3], bh[p][0], bh[p][1]);
                MMA_BF16(acc[mi][2*p+1], ah[mi][0], ah[mi][1], ah[mi][2], ah[mi][3], bh[p][2], bh[p][3]);
                MMA_BF16(acc[mi][2*p],   al[mi][0], al[mi][1], al[mi][2], al[mi][3], bh[p][0], bh[p][1]);
                MMA_BF16(acc[mi][2*p+1], al[mi][0], al[mi][1], al[mi][2], al[mi][3], bh[p][2], bh[p][3]);
                MMA_BF16(acc[mi][2*p],   ah[mi][0], ah[mi][1], ah[mi][2], ah[mi][3], bl[p][0], bl[p][1]);
                MMA_BF16(acc[mi][2*p+1], ah[mi][0], ah[mi][1], ah[mi][2], ah[mi][3], bl[p][2], bl[p][3]);
            }

        __syncthreads();
        if (st + 2 < NST) {
            int k0 = (st + 2) << 4;
            uint32_t dsA = (uint32_t)s * 12288u;
            uint32_t dsB = (uint32_t)s * 6144u;
            CP_ASYNC16(dA + dsA,        gAh + k0);
            CP_ASYNC16(dA + dsA + 6144, gAl + k0);
            CP_ASYNC16(dB + dsB,        gB + k0);
            CP_COMMIT();
        }
    }

    int crow = lane >> 2, ccol = (lane & 3) * 2;
    #pragma unroll
    for (int mi = 0; mi < 2; mi++) {
        int m = m0 + warp_m * 32 + mi * 16 + crow;
        #pragma unroll
        for (int nj = 0; nj < 4; nj++) {
            int n = n0 + warp_n * 32 + nj * 8 + ccol;
            float v0 = acc[mi][nj][0], v1 = acc[mi][nj][1];
            float v2 = acc[mi][nj][2], v3 = acc[mi][nj][3];
            if (BIAS) {
                float b0 = bias[n], b1 = bias[n + 1];
                v0 += b0; v1 += b1; v2 += b0; v3 += b1;
            }
            if (GELU) {
                v0 = 0.5f * v0 * (1.0f + erff(v0 * 0.70710678118654752f));
                v1 = 0.5f * v1 * (1.0f + erff(v1 * 0.70710678118654752f));
                v2 = 0.5f * v2 * (1.0f + erff(v2 * 0.70710678118654752f));
                v3 = 0.5f * v3 * (1.0f + erff(v3 * 0.70710678118654752f));
            }
            size_t o0 = (size_t)m * N + n;
            size_t o1 = (size_t)(m + 8) * N + n;
            if (OSPLIT) {
                uint32_t hi, lo;
                split2(v0, v1, hi, lo);
                ((uint32_t*)g_Bhi)[o0 >> 1] = hi;
                ((uint32_t*)g_Blo)[o0 >> 1] = lo;
                split2(v2, v3, hi, lo);
                ((uint32_t*)g_Bhi)[o1 >> 1] = hi;
                ((uint32_t*)g_Blo)[o1 >> 1] = lo;
            } else {
                if (RES) {
                    float2 r0 = *(float2*)&C[o0];
                    float2 r1 = *(float2*)&C[o1];
                    v0 += r0.x; v1 += r0.y; v2 += r1.x; v3 += r1.y;
                }
                *(float2*)&C[o0] = make_float2(v0, v1);
                *(float2*)&C[o1] = make_float2(v2, v3);
            }
        }
    }
}

// ---------------- qkv split + rope -> bf16 hi/lo ----------------
__global__ void __launch_bounds__(256) qkv_rope_k() {
    int idx = blockIdx.x * 256 + threadIdx.x;      // bh*65536 + s*64 + d
    int d  = idx & 63;
    int s  = (idx >> 6) & (Sv - 1);
    int bh = idx >> 16;
    int b = bh >> 4, h = bh & 15;
    const float* u = g_U + ((size_t)(b * Sv + s)) * (3 * Tv) + h * 64;
    float uq = u[d], uk = u[Tv + d], uv = u[2 * Tv + d];
    int i  = d & 31;
    int d2 = (d < 32) ? d + 32 : d - 32;
    float uq2 = u[d2], uk2 = u[Tv + d2];
    float invf = powf(10000.0f, -(float)i / 32.0f);
    float ang = (float)s * invf;
    float c, sn;
    sincosf(ang, &sn, &c);
    float sgn = (d < 32) ? -1.0f : 1.0f;
    float q = uq * c + sgn * uq2 * sn;
    float k = uk * c + sgn * uk2 * sn;
    __nv_bfloat16 qh = __float2bfloat16(q);
    __nv_bfloat16 kh = __float2bfloat16(k);
    __nv_bfloat16 vh = __float2bfloat16(uv);
    g_Qh[idx] = qh; g_Ql[idx] = __float2bfloat16(q - __bfloat162float(qh));
    g_Kh[idx] = kh; g_Kl[idx] = __float2bfloat16(k - __bfloat162float(kh));
    g_Vh[idx] = vh; g_Vl[idx] = __float2bfloat16(uv - __bfloat162float(vh));
}

// ---------------- V transpose: [bh][s][d] -> [bh][d][s] ----------------
__global__ void __launch_bounds__(256) vT_k() {
    __shared__ uint16_t t[2][64][65];
    int bh = blockIdx.y, s0 = blockIdx.x * 64;
    size_t base = (size_t)bh * Sv * HDv;
    const uint16_t* Vh = (const uint16_t*)g_Vh;
    const uint16_t* Vl = (const uint16_t*)g_Vl;
    uint16_t* Th = (uint16_t*)g_VTh;
    uint16_t* Tl = (uint16_t*)g_VTl;
    #pragma unroll
    for (int i = 0; i < 16; i++) {
        int f = threadIdx.x + i * 256;
        int sr = f >> 6, dc = f & 63;
        size_t g = base + (size_t)(s0 + sr) * HDv + dc;
        t[0][sr][dc] = Vh[g];
        t[1][sr][dc] = Vl[g];
    }
    __syncthreads();
    #pragma unroll
    for (int i = 0; i < 16; i++) {
        int f = threadIdx.x + i * 256;
        int d = f >> 6, ss = f & 63;
        size_t g = base + (size_t)d * Sv + s0 + ss;
        Th[g] = t[0][ss][d];
        Tl[g] = t[1][ss][d];
    }
}

// =====================================================================
// attention scores (tensorized): P = Q K^T / 8, 64x64 tiles, causal skip
// =====================================================================
__global__ void __launch_bounds__(128) attn_scores_mma() {
    int bh = blockIdx.z;
    int q0 = blockIdx.y * 64, k0 = blockIdx.x * 64;
    if (k0 > q0 + 63) return;
    __shared__ __align__(16) uint8_t sQ[2][9216];   // [hi/lo][64 rows * 144B]
    __shared__ __align__(16) uint8_t sK[2][9216];

    int tid = threadIdx.x, lane = tid & 31, w = tid >> 5;
    size_t base = (size_t)bh * Sv * HDv;
    uint32_t qS = smem_to_u32(&sQ[0][0]);
    uint32_t kS = smem_to_u32(&sK[0][0]);

    #pragma unroll
    for (int i = 0; i < 4; i++) {
        int f = tid + i * 128;
        int row = f >> 3, seg = f & 7;
        uint32_t so = (uint32_t)(row * 144 + seg * 16);
        size_t gq = base + (size_t)(q0 + row) * HDv + seg * 8;
        size_t gk = base + (size_t)(k0 + row) * HDv + seg * 8;
        CP_ASYNC16(qS + so,        g_Qh + gq);
        CP_ASYNC16(qS + 9216 + so, g_Ql + gq);
        CP_ASYNC16(kS + so,        g_Kh + gk);
        CP_ASYNC16(kS + 9216 + so, g_Kl + gk);
    }
    CP_COMMIT(); CP_WAIT0();
    __syncthreads();

    float acc[8][4];
    #pragma unroll
    for (int nj = 0; nj < 8; nj++)
        #pragma unroll
        for (int q = 0; q < 4; q++) acc[nj][q] = 0.f;

    int a_row = lane & 15, a_chunk = lane >> 4;
    int b_row = (lane & 7) | ((lane >> 4) << 3);
    int b_chunk = (lane >> 3) & 1;
    uint32_t aB = qS + (uint32_t)((w * 16 + a_row) * 144 + a_chunk * 16);
    uint32_t bB = kS + (uint32_t)(b_row * 144 + b_chunk * 16);

    #pragma unroll
    for (int ks = 0; ks < 4; ks++) {
        uint32_t ah[4], al[4];
        LDSM_X4(ah[0], ah[1], ah[2], ah[3], aB + ks * 32u);
        LDSM_X4(al[0], al[1], al[2], al[3], aB + 9216u + ks * 32u);
        #pragma unroll
        for (int g = 0; g < 4; g++) {
            uint32_t b0, b1, b2, b3;
            LDSM_X4(b0, b1, b2, b3, bB + g * 2304u + ks * 32u);
            MMA_BF16(acc[2*g],   ah[0], ah[1], ah[2], ah[3], b0, b1);
            MMA_BF16(acc[2*g+1], ah[0], ah[1], ah[2], ah[3], b2, b3);
            MMA_BF16(acc[2*g],   al[0], al[1], al[2], al[3], b0, b1);
            MMA_BF16(acc[2*g+1], al[0], al[1], al[2], al[3], b2, b3);
            LDSM_X4(b0, b1, b2, b3, bB + 9216u + g * 2304u + ks * 32u);
            MMA_BF16(acc[2*g],   ah[0], ah[1], ah[2], ah[3], b0, b1);
            MMA_BF16(acc[2*g+1], ah[0], ah[1], ah[2], ah[3], b2, b3);
        }
    }

    float* out = g_P + (size_t)bh * Sv * Sv;
    int crow = lane >> 2, ccol = (lane & 3) * 2;
    int qq = q0 + w * 16 + crow;
    #pragma unroll
    for (int nj = 0; nj < 8; nj++) {
        int kk = k0 + nj * 8 + ccol;
        out[(size_t)qq * Sv + kk]       = acc[nj][0] * 0.125f;
        out[(size_t)qq * Sv + kk + 1]   = acc[nj][1] * 0.125f;
        out[(size_t)(qq+8) * Sv + kk]   = acc[nj][2] * 0.125f;
        out[(size_t)(qq+8) * Sv + kk+1] = acc[nj][3] * 0.125f;
    }
}

// ---------------- causal softmax: fp32 scores -> bf16 hi/lo probs ----------------
__global__ void __launch_bounds__(256) attn_softmax_k() {
    __shared__ float red[8];
    int idx = blockIdx.x;            // bh*S + q
    int q = idx & (Sv - 1);
    float* row = g_P + (size_t)idx * Sv;
    int len = q + 1;
    int kup = ((q >> 6) + 1) << 6;
    int tid = threadIdx.x;
    float mx = -1e30f;
    for (int k = tid; k < len; k += 256) mx = fmaxf(mx, row[k]);
    mx = block_max(mx, red);
    float sum = 0.f;
    for (int k = tid; k < len; k += 256) {
        float e = expf(row[k] - mx);
        row[k] = e;
        sum += e;
    }
    sum = block_sum(sum, red);
    float inv = 1.0f / sum;
    for (int k = tid; k < kup; k += 256) {
        float p = (k < len) ? row[k] * inv : 0.0f;
        __nv_bfloat16 ph = __float2bfloat16(p);
        g_Phi[(size_t)idx * Sv + k] = ph;
        g_Plo[(size_t)idx * Sv + k] = __float2bfloat16(p - __bfloat162float(ph));
    }
}

// =====================================================================
// PV (tensorized): AO[q][d] = P[q][k] * VT[d][k], causal K-bound.
// =====================================================================
__global__ void __launch_bounds__(128) attn_pv_mma() {
    int bh = blockIdx.y;
    int q0 = blockIdx.x * 64;
    __shared__ __align__(16) uint8_t sP[2][9216];
    __shared__ __align__(16) uint8_t sV[2][9216];

    int tid = threadIdx.x, lane = tid & 31, w = tid >> 5;
    size_t pBase = (size_t)(bh * Sv) * Sv;
    size_t vBase = (size_t)bh * Sv * HDv;
    uint32_t pS = smem_to_u32(&sP[0][0]);
    uint32_t vS = smem_to_u32(&sV[0][0]);

    float acc[8][4];
    #pragma unroll
    for (int nj = 0; nj < 8; nj++)
        #pragma unroll
        for (int q = 0; q < 4; q++) acc[nj][q] = 0.f;

    int a_row = lane & 15, a_chunk = lane >> 4;
    int b_row = (lane & 7) | ((lane >> 4) << 3);
    int b_chunk = (lane >> 3) & 1;
    uint32_t aB = pS + (uint32_t)((w * 16 + a_row) * 144 + a_chunk * 16);
    uint32_t bB = vS + (uint32_t)(b_row * 144 + b_chunk * 16);

    int kmax = q0 + 64;
    for (int kc = 0; kc < kmax; kc += 64) {
        #pragma unroll
        for (int i = 0; i < 4; i++) {
            int f = tid + i * 128;
            int row = f >> 3, seg = f & 7;
            uint32_t so = (uint32_t)(row * 144 + seg * 16);
            size_t gp = pBase + (size_t)(q0 + row) * Sv + kc + seg * 8;
            size_t gv = vBase + (size_t)row * Sv + kc + seg * 8;
            CP_ASYNC16(pS + so,        g_Phi + gp);
            CP_ASYNC16(pS + 9216 + so, g_Plo + gp);
            CP_ASYNC16(vS + so,        g_VTh + gv);
            CP_ASYNC16(vS + 9216 + so, g_VTl + gv);
        }
        CP_COMMIT(); CP_WAIT0();
        __syncthreads();

        #pragma unroll
        for (int ks = 0; ks < 4; ks++) {
            uint32_t ah[4], al[4];
            LDSM_X4(ah[0], ah[1], ah[2], ah[3], aB + ks * 32u);
            LDSM_X4(al[0], al[1], al[2], al[3], aB + 9216u + ks * 32u);
            #pragma unroll
            for (int g = 0; g < 4; g++) {
                uint32_t b0, b1, b2, b3;
                LDSM_X4(b0, b1, b2, b3, bB + g * 2304u + ks * 32u);
                MMA_BF16(acc[2*g],   ah[0], ah[1], ah[2], ah[3], b0, b1);
                MMA_BF16(acc[2*g+1], ah[0], ah[1], ah[2], ah[3], b2, b3);
                MMA_BF16(acc[2*g],   al[0], al[1], al[2], al[3], b0, b1);
                MMA_BF16(acc[2*g+1], al[0], al[1], al[2], al[3], b2, b3);
                LDSM_X4(b0, b1, b2, b3, bB + 9216u + g * 2304u + ks * 32u);
                MMA_BF16(acc[2*g],   ah[0], ah[1], ah[2], ah[3], b0, b1);
                MMA_BF16(acc[2*g+1], ah[0], ah[1], ah[2], ah[3], b2, b3);
            }
        }
        __syncthreads();
    }

    int b = bh >> 4, h = bh & 15;
    int crow = lane >> 2, ccol = (lane & 3) * 2;
    int q = q0 + w * 16 + crow;
    #pragma unroll
    for (int nj = 0; nj < 8; nj++) {
        int d = nj * 8 + ccol;
        uint32_t hi, lo;
        split2(acc[nj][0], acc[nj][1], hi, lo);
        size_t o0 = (size_t)(b * Sv + q) * Tv + h * 64 + d;
        *(uint32_t*)&g_Ahi[o0] = hi;
        *(uint32_t*)&g_Alo[o0] = lo;
        split2(acc[nj][2], acc[nj][3], hi, lo);
        size_t o1 = (size_t)(b * Sv + q + 8) * Tv + h * 64 + d;
        *(uint32_t*)&g_Ahi[o1] = hi;
        *(uint32_t*)&g_Alo[o1] = lo;
    }
}

// ---------------- launch (kernel launches ONLY) ----------------
extern "C" void kernel_launch(void* const* d_in, const int* in_sizes, int n_in,
                              void* d_out, int out_size) {
    const int*   ids = (const int*)  d_in[0];
    const float* emb = (const float*)d_in[1];
    const float* Wu  = (const float*)d_in[2];
    const float* Wo  = (const float*)d_in[3];
    const float* n1w = (const float*)d_in[4];
    const float* n1b = (const float*)d_in[5];
    const float* n2w = (const float*)d_in[6];
    const float* n2b = (const float*)d_in[7];
    const float* f1w = (const float*)d_in[8];
    const float* f1b = (const float*)d_in[9];
    const float* f2w = (const float*)d_in[10];
    const float* f2b = (const float*)d_in[11];
    const float* fnw = (const float*)d_in[12];
    const float* fnb = (const float*)d_in[13];
    float* out = (float*)d_out;

    // front-load so the QKV gemm is launch #4 (ncu capture window)
    embed_k<<<BS, 256>>>(ids, emb);
    conv_w_k<<<(int)((N_WU/4  + 255) / 256), 256>>>(Wu,  OFF_WU,  (int)(N_WU/4));
    layernorm_split_k<<<BS, 256>>>(n1w, n1b);
    gemm_mma<false, false, false, false><<<dim3(BS / 128, 3 * Tv / 64), 256>>>(
        OFF_WU, nullptr, nullptr, SEL_U, 0, BS, 3 * Tv, Dv);
    conv_w_k<<<(int)((N_WO/4  + 255) / 256), 256>>>(Wo,  OFF_WO,  (int)(N_WO/4));
    conv_w_k<<<(int)((N_F1/4  + 255) / 256), 256>>>(f1w, OFF_F1,  (int)(N_F1/4));
    conv_w_k<<<(int)((N_F2/4  + 255) / 256), 256>>>(f2w, OFF_F2,  (int)(N_F2/4));
    conv_w_k<<<(int)((N_EMB/4 + 255) / 256), 256>>>(emb, OFF_EMB, (int)(N_EMB/4));

    for (int l = 0; l < Lv; l++) {
        if (l > 0) {
            layernorm_split_k<<<BS, 256>>>(n1w + l * Dv, n1b + l * Dv);
            gemm_mma<false, false, false, false><<<dim3(BS / 128, 3 * Tv / 64), 256>>>(
                OFF_WU + (size_t)l * 3 * Tv * Dv, nullptr, nullptr, SEL_U, 0, BS, 3 * Tv, Dv);
        }
        qkv_rope_k<<<(BHv * Sv * HDv) / 256, 256>>>();
        vT_k<<<dim3(Sv / 64, BHv), 256>>>();
        attn_scores_mma<<<dim3(Sv / 64, Sv / 64, BHv), 128>>>();
        attn_softmax_k<<<BHv * Sv, 256>>>();
        attn_pv_mma<<<dim3(Sv / 64, BHv), 128>>>();
        gemm_mma<false, false, true, false><<<dim3(BS / 128, Dv / 64), 256>>>(
            OFF_WO + (size_t)l * Dv * Tv, nullptr, nullptr, SEL_X, 0, BS, Dv, Tv);

        layernorm_split_k<<<BS, 256>>>(n2w + l * Dv, n2b + l * Dv);
        gemm_mma<true, true, false, true><<<dim3(BS / 128, FFv / 64), 256>>>(
            OFF_F1 + (size_t)l * FFv * Dv, f1b + (size_t)l * FFv, nullptr, -1, 0, BS, FFv, Dv);
        gemm_mma<true, false, true, false><<<dim3(BS / 128, Dv / 64), 256>>>(
            OFF_F2 + (size_t)l * Dv * FFv, f2b + (size_t)l * Dv, nullptr, SEL_X, 1, BS, Dv, FFv);
    }

    // ---- final LN + tied-embedding logits ----
    layernorm_split_k<<<BS, 256>>>(fnw, fnb);
    gemm_mma<false, false, false, false><<<dim3(BS / 128, Vv / 64), 256>>>(
        OFF_EMB, nullptr, out, -1, 0, BS, Vv, Dv);
}

// round 14
// speedup vs baseline: 1.0906x; 1.0691x over previous
#include <cuda_runtime.h>
#include <cuda_bf16.h>
#include <math.h>
#include <cstdint>

// ---------------- problem dims ----------------
#define Bv   2
#define Sv   1024
#define Dv   1024
#define Hh   16
#define HDv  64
#define Tv   1024
#define FFv  4096
#define Lv   8
#define Vv   32000
#define BS   (Bv*Sv)     // 2048
#define BHv  (Bv*Hh)     // 32

// ============ PTX helpers (baseline PTX only: sm_80-class features) ============
__device__ __forceinline__ uint32_t smem_to_u32(const void* p) {
    uint32_t a;
    asm("{ .reg .u64 t; cvta.to.shared.u64 t, %1; cvt.u32.u64 %0, t; }" : "=r"(a) : "l"(p));
    return a;
}
#define CP_ASYNC16(dst, src) \
    asm volatile("cp.async.cg.shared.global [%0], [%1], 16;" :: "r"(dst), "l"(src))
#define CP_COMMIT() asm volatile("cp.async.commit_group;" ::: "memory")
#define CP_WAIT1()  asm volatile("cp.async.wait_group 1;" ::: "memory")
#define CP_WAIT0()  asm volatile("cp.async.wait_group 0;" ::: "memory")
#define LDSM_X4(R0, R1, R2, R3, ADDR) \
    asm volatile("ldmatrix.sync.aligned.m8n8.x4.shared.b16 {%0,%1,%2,%3}, [%4];" \
        : "=r"(R0), "=r"(R1), "=r"(R2), "=r"(R3) : "r"(ADDR))
#define MMA_BF16(D, A0, A1, A2, A3, B0, B1) \
    asm volatile("mma.sync.aligned.m16n8k16.row.col.f32.bf16.bf16.f32 " \
        "{%0,%1,%2,%3},{%4,%5,%6,%7},{%8,%9},{%0,%1,%2,%3};" \
        : "+f"((D)[0]), "+f"((D)[1]), "+f"((D)[2]), "+f"((D)[3]) \
        : "r"(A0), "r"(A1), "r"(A2), "r"(A3), "r"(B0), "r"(B1))

// ---------------- scratch (device globals; no allocations, no host API) ----------------
__device__ float g_X [BS*Dv];
__device__ float g_U [BS*3*Tv];
__device__ float g_P [(size_t)BHv*Sv*Sv];           // fp32 scores

// attention bf16 hi/lo buffers
__device__ __nv_bfloat16 g_Qh[BHv*Sv*HDv], g_Ql[BHv*Sv*HDv];
__device__ __nv_bfloat16 g_Kh[BHv*Sv*HDv], g_Kl[BHv*Sv*HDv];
__device__ __nv_bfloat16 g_Vh[BHv*Sv*HDv], g_Vl[BHv*Sv*HDv];
__device__ __nv_bfloat16 g_VTh[BHv*Sv*HDv], g_VTl[BHv*Sv*HDv];   // [bh][d][s]
__device__ __nv_bfloat16 g_Phi[(size_t)BHv*Sv*Sv], g_Plo[(size_t)BHv*Sv*Sv];

// bf16 hi/lo split weights
#define N_WU  ((size_t)Lv*3*Tv*Dv)
#define N_WO  ((size_t)Lv*Dv*Tv)
#define N_F1  ((size_t)Lv*FFv*Dv)
#define N_F2  ((size_t)Lv*Dv*FFv)
#define N_EMB ((size_t)Vv*Dv)
#define OFF_WU  0ull
#define OFF_WO  (OFF_WU + N_WU)
#define OFF_F1  (OFF_WO + N_WO)
#define OFF_F2  (OFF_F1 + N_F1)
#define OFF_EMB (OFF_F2 + N_F2)
#define N_WTOT  (OFF_EMB + N_EMB)
__device__ __nv_bfloat16 g_Whi[N_WTOT];
__device__ __nv_bfloat16 g_Wlo[N_WTOT];
// split activations: A ping (LN out / attn out), B pong (F1 out -> F2 in).
__device__ __nv_bfloat16 g_Ahi[(size_t)BS*Dv],  g_Alo[(size_t)BS*Dv];
__device__ __nv_bfloat16 g_Bhi[(size_t)BS*FFv], g_Blo[(size_t)BS*FFv];

// fp32 C-output selectors (device-side; avoids host symbol API)
#define SEL_U  0
#define SEL_X  1
__device__ __forceinline__ float* sel_buf(int s, float* ext) {
    switch (s) {
        case SEL_U: return g_U;
        case SEL_X: return g_X;
    }
    return ext;
}

// ---------------- reductions ----------------
__device__ __forceinline__ float block_sum(float v, float* red) {
    #pragma unroll
    for (int o = 16; o; o >>= 1) v += __shfl_xor_sync(0xffffffffu, v, o);
    if ((threadIdx.x & 31) == 0) red[threadIdx.x >> 5] = v;
    __syncthreads();
    float t = 0.f;
    #pragma unroll
    for (int w = 0; w < 8; w++) t += red[w];
    __syncthreads();
    return t;
}
__device__ __forceinline__ float block_max(float v, float* red) {
    #pragma unroll
    for (int o = 16; o; o >>= 1) v = fmaxf(v, __shfl_xor_sync(0xffffffffu, v, o));
    if ((threadIdx.x & 31) == 0) red[threadIdx.x >> 5] = v;
    __syncthreads();
    float t = -1e30f;
    #pragma unroll
    for (int w = 0; w < 8; w++) t = fmaxf(t, red[w]);
    __syncthreads();
    return t;
}

// ---------------- hi/lo split ----------------
__device__ __forceinline__ void split2(float x, float y, uint32_t& hi, uint32_t& lo) {
    __nv_bfloat16 hx = __float2bfloat16(x);
    __nv_bfloat16 hy = __float2bfloat16(y);
    __nv_bfloat16 lx = __float2bfloat16(x - __bfloat162float(hx));
    __nv_bfloat16 ly = __float2bfloat16(y - __bfloat162float(hy));
    __nv_bfloat162 h2 = __nv_bfloat162(hx, hy);
    __nv_bfloat162 l2 = __nv_bfloat162(lx, ly);
    hi = *(uint32_t*)&h2;
    lo = *(uint32_t*)&l2;
}
__global__ void __launch_bounds__(256) conv_w_k(const float* __restrict__ src, size_t off, int n4) {
    int i = blockIdx.x * 256 + threadIdx.x;
    if (i >= n4) return;
    float4 v = ((const float4*)src)[i];
    uint32_t h0, l0, h1, l1;
    split2(v.x, v.y, h0, l0);
    split2(v.z, v.w, h1, l1);
    uint32_t* dh = (uint32_t*)(g_Whi + off);
    uint32_t* dl = (uint32_t*)(g_Wlo + off);
    dh[2*i] = h0; dh[2*i+1] = h1;
    dl[2*i] = l0; dl[2*i+1] = l1;
}

// ---------------- embedding gather ----------------
__global__ void __launch_bounds__(256) embed_k(const int* __restrict__ ids,
                                               const float* __restrict__ emb) {
    int r = blockIdx.x;
    int id = ids[r];
    float4 v = ((const float4*)(emb + (size_t)id * Dv))[threadIdx.x];
    ((float4*)(g_X + (size_t)r * Dv))[threadIdx.x] = v;
}

// ---------------- layernorm fused with hi/lo split -> g_Ahi/g_Alo ----------------
__global__ void __launch_bounds__(256) layernorm_split_k(const float* __restrict__ w,
                                                         const float* __restrict__ b) {
    __shared__ float red[8];
    int r = blockIdx.x, tid = threadIdx.x;
    float4 v = ((const float4*)(g_X + (size_t)r * Dv))[tid];
    float s = block_sum(v.x + v.y + v.z + v.w, red);
    float mu = s * (1.0f / Dv);
    float dx = v.x - mu, dy = v.y - mu, dz = v.z - mu, dw = v.w - mu;
    float sq = block_sum(dx*dx + dy*dy + dz*dz + dw*dw, red);
    float inv = rsqrtf(sq * (1.0f / Dv) + 1e-5f);
    float4 wv = ((const float4*)w)[tid];
    float4 bv = ((const float4*)b)[tid];
    float ox = dx * inv * wv.x + bv.x;
    float oy = dy * inv * wv.y + bv.y;
    float oz = dz * inv * wv.z + bv.z;
    float ow = dw * inv * wv.w + bv.w;
    uint32_t h0, l0, h1, l1;
    split2(ox, oy, h0, l0);
    split2(oz, ow, h1, l1);
    size_t base = ((size_t)r * Dv) / 2 + tid * 2;
    ((uint32_t*)g_Ahi)[base] = h0; ((uint32_t*)g_Ahi)[base + 1] = h1;
    ((uint32_t*)g_Alo)[base] = l0; ((uint32_t*)g_Alo)[base + 1] = l1;
}

// =====================================================================
// bf16 split-precision MMA GEMM: C(MxN) = A(MxK)*B(NxK)^T
// CTA tile 128x128 (8 warps 2x4, warp tile 64x32) — best measured shape.
// 3-stage cp.async pipeline, ONE __syncthreads per K-stage (CUTLASS sm80
// pattern): top barrier frees buffer (st+2)%3 (read in stage st-1), then
// prefetch for st+2 is issued and stays in flight through stage st compute.
// asel: 0 = A from g_Ahi/g_Alo, 1 = A from g_Bhi/g_Blo.
// OSPLIT: epilogue writes bf16 hi/lo into g_Bhi/g_Blo.
// =====================================================================
template<bool BIAS, bool GELU, bool RES, bool OSPLIT>
__global__ void __launch_bounds__(256, 2) gemm_mma(size_t wOff,
                                                   const float* __restrict__ bias,
                                                   float* __restrict__ extC,
                                                   int csel, int asel,
                                                   int M, int N, int K) {
    __shared__ __align__(16) uint8_t sA[3][2][6144];  // [stage][hi/lo][128 rows * 48B]
    __shared__ __align__(16) uint8_t sB[3][2][6144];

    int tid = threadIdx.x, lane = tid & 31, wid = tid >> 5;
    int warp_m = wid >> 2, warp_n = wid & 3;          // 2 x 4, warp tile 64x32
    int m0 = blockIdx.x * 128, n0 = blockIdx.y * 128;
    float* C = OSPLIT ? nullptr : ((csel >= 0) ? sel_buf(csel, nullptr) : extC);
    const __nv_bfloat16* Ahi = asel ? g_Bhi : g_Ahi;
    const __nv_bfloat16* Alo = asel ? g_Blo : g_Alo;

    int r = tid >> 1, h = tid & 1;
    const __nv_bfloat16* gAh = Ahi + (size_t)(m0 + r) * K + h * 8;
    const __nv_bfloat16* gAl = Alo + (size_t)(m0 + r) * K + h * 8;
    const __nv_bfloat16* gBh = g_Whi + wOff + (size_t)(n0 + r) * K + h * 8;
    const __nv_bfloat16* gBl = g_Wlo + wOff + (size_t)(n0 + r) * K + h * 8;
    uint32_t aS = smem_to_u32(&sA[0][0][0]);
    uint32_t bS = smem_to_u32(&sB[0][0][0]);
    uint32_t dA = aS + r * 48 + h * 16;
    uint32_t dB = bS + r * 48 + h * 16;

    float acc[4][4][4];
    #pragma unroll
    for (int mi = 0; mi < 4; mi++)
        #pragma unroll
        for (int nj = 0; nj < 4; nj++)
            #pragma unroll
            for (int q = 0; q < 4; q++) acc[mi][nj][q] = 0.f;

    const int NST = K >> 4;
    // prologue: stages 0,1 in flight (one commit group each)
    #pragma unroll
    for (int p = 0; p < 2; p++) {
        uint32_t ds = (uint32_t)p * 12288u;
        CP_ASYNC16(dA + ds,        gAh + p * 16);
        CP_ASYNC16(dA + ds + 6144, gAl + p * 16);
        CP_ASYNC16(dB + ds,        gBh + p * 16);
        CP_ASYNC16(dB + ds + 6144, gBl + p * 16);
        CP_COMMIT();
    }

    int a_row = lane & 15, a_chunk = lane >> 4;
    int b_row = (lane & 7) | ((lane >> 4) << 3);
    int b_chunk = (lane >> 3) & 1;
    uint32_t aAddr0 = aS + (uint32_t)((warp_m * 64 + a_row) * 48 + a_chunk * 16);
    uint32_t bAddr0 = bS + (uint32_t)((warp_n * 32 + b_row) * 48 + b_chunk * 16);

    int buf = 0;                      // st % 3
    int nbuf = 2;                     // (st+2) % 3
    for (int st = 0; st < NST; st++) {
        if (st + 2 < NST) { CP_WAIT1(); } else { CP_WAIT0(); }
        __syncthreads();              // frees buffer nbuf (read in stage st-1)

        if (st + 2 < NST) {
            int k0 = (st + 2) << 4;
            uint32_t ds = (uint32_t)nbuf * 12288u;
            CP_ASYNC16(dA + ds,        gAh + k0);
            CP_ASYNC16(dA + ds + 6144, gAl + k0);
            CP_ASYNC16(dB + ds,        gBh + k0);
            CP_ASYNC16(dB + ds + 6144, gBl + k0);
            CP_COMMIT();
        }

        uint32_t aBase = aAddr0 + (uint32_t)buf * 12288u;
        uint32_t bBase = bAddr0 + (uint32_t)buf * 12288u;

        uint32_t ah[4][4], al[4][4];
        #pragma unroll
        for (int mi = 0; mi < 4; mi++)
            LDSM_X4(ah[mi][0], ah[mi][1], ah[mi][2], ah[mi][3], aBase + mi * 768u);
        #pragma unroll
        for (int mi = 0; mi < 4; mi++)
            LDSM_X4(al[mi][0], al[mi][1], al[mi][2], al[mi][3], aBase + 6144u + mi * 768u);

        #pragma unroll
        for (int p = 0; p < 2; p++) {
            uint32_t b0, b1, b2, b3;
            LDSM_X4(b0, b1, b2, b3, bBase + p * 768u);
            #pragma unroll
            for (int mi = 0; mi < 4; mi++) {
                MMA_BF16(acc[mi][2*p],   ah[mi][0], ah[mi][1], ah[mi][2], ah[mi][3], b0, b1);
                MMA_BF16(acc[mi][2*p+1], ah[mi][0], ah[mi][1], ah[mi][2], ah[mi][3], b2, b3);
                MMA_BF16(acc[mi][2*p],   al[mi][0], al[mi][1], al[mi][2], al[mi][3], b0, b1);
                MMA_BF16(acc[mi][2*p+1], al[mi][0], al[mi][1], al[mi][2], al[mi][3], b2, b3);
            }
            LDSM_X4(b0, b1, b2, b3, bBase + 6144u + p * 768u);
            #pragma unroll
            for (int mi = 0; mi < 4; mi++) {
                MMA_BF16(acc[mi][2*p],   ah[mi][0], ah[mi][1], ah[mi][2], ah[mi][3], b0, b1);
                MMA_BF16(acc[mi][2*p+1], ah[mi][0], ah[mi][1], ah[mi][2], ah[mi][3], b2, b3);
            }
        }

        buf = (buf == 2) ? 0 : buf + 1;
        nbuf = (nbuf == 2) ? 0 : nbuf + 1;
    }

    int crow = lane >> 2, ccol = (lane & 3) * 2;
    #pragma unroll
    for (int mi = 0; mi < 4; mi++) {
        int m = m0 + warp_m * 64 + mi * 16 + crow;
        #pragma unroll
        for (int nj = 0; nj < 4; nj++) {
            int n = n0 + warp_n * 32 + nj * 8 + ccol;
            float v0 = acc[mi][nj][0], v1 = acc[mi][nj][1];
            float v2 = acc[mi][nj][2], v3 = acc[mi][nj][3];
            if (BIAS) {
                float b0 = bias[n], b1 = bias[n + 1];
                v0 += b0; v1 += b1; v2 += b0; v3 += b1;
            }
            if (GELU) {
                v0 = 0.5f * v0 * (1.0f + erff(v0 * 0.70710678118654752f));
                v1 = 0.5f * v1 * (1.0f + erff(v1 * 0.70710678118654752f));
                v2 = 0.5f * v2 * (1.0f + erff(v2 * 0.70710678118654752f));
                v3 = 0.5f * v3 * (1.0f + erff(v3 * 0.70710678118654752f));
            }
            size_t o0 = (size_t)m * N + n;
            size_t o1 = (size_t)(m + 8) * N + n;
            if (OSPLIT) {
                uint32_t hi, lo;
                split2(v0, v1, hi, lo);
                ((uint32_t*)g_Bhi)[o0 >> 1] = hi;
                ((uint32_t*)g_Blo)[o0 >> 1] = lo;
                split2(v2, v3, hi, lo);
                ((uint32_t*)g_Bhi)[o1 >> 1] = hi;
                ((uint32_t*)g_Blo)[o1 >> 1] = lo;
            } else {
                if (RES) {
                    float2 r0 = *(float2*)&C[o0];
                    float2 r1 = *(float2*)&C[o1];
                    v0 += r0.x; v1 += r0.y; v2 += r1.x; v3 += r1.y;
                }
                *(float2*)&C[o0] = make_float2(v0, v1);
                *(float2*)&C[o1] = make_float2(v2, v3);
            }
        }
    }
}

// ---------------- qkv split + rope -> bf16 hi/lo ----------------
__global__ void __launch_bounds__(256) qkv_rope_k() {
    int idx = blockIdx.x * 256 + threadIdx.x;      // bh*65536 + s*64 + d
    int d  = idx & 63;
    int s  = (idx >> 6) & (Sv - 1);
    int bh = idx >> 16;
    int b = bh >> 4, h = bh & 15;
    const float* u = g_U + ((size_t)(b * Sv + s)) * (3 * Tv) + h * 64;
    float uq = u[d], uk = u[Tv + d], uv = u[2 * Tv + d];
    int i  = d & 31;
    int d2 = (d < 32) ? d + 32 : d - 32;
    float uq2 = u[d2], uk2 = u[Tv + d2];
    float invf = powf(10000.0f, -(float)i / 32.0f);
    float ang = (float)s * invf;
    float c, sn;
    sincosf(ang, &sn, &c);
    float sgn = (d < 32) ? -1.0f : 1.0f;
    float q = uq * c + sgn * uq2 * sn;
    float k = uk * c + sgn * uk2 * sn;
    __nv_bfloat16 qh = __float2bfloat16(q);
    __nv_bfloat16 kh = __float2bfloat16(k);
    __nv_bfloat16 vh = __float2bfloat16(uv);
    g_Qh[idx] = qh; g_Ql[idx] = __float2bfloat16(q - __bfloat162float(qh));
    g_Kh[idx] = kh; g_Kl[idx] = __float2bfloat16(k - __bfloat162float(kh));
    g_Vh[idx] = vh; g_Vl[idx] = __float2bfloat16(uv - __bfloat162float(vh));
}

// ---------------- V transpose: [bh][s][d] -> [bh][d][s] ----------------
__global__ void __launch_bounds__(256) vT_k() {
    __shared__ uint16_t t[2][64][65];
    int bh = blockIdx.y, s0 = blockIdx.x * 64;
    size_t base = (size_t)bh * Sv * HDv;
    const uint16_t* Vh = (const uint16_t*)g_Vh;
    const uint16_t* Vl = (const uint16_t*)g_Vl;
    uint16_t* Th = (uint16_t*)g_VTh;
    uint16_t* Tl = (uint16_t*)g_VTl;
    #pragma unroll
    for (int i = 0; i < 16; i++) {
        int f = threadIdx.x + i * 256;
        int sr = f >> 6, dc = f & 63;
        size_t g = base + (size_t)(s0 + sr) * HDv + dc;
        t[0][sr][dc] = Vh[g];
        t[1][sr][dc] = Vl[g];
    }
    __syncthreads();
    #pragma unroll
    for (int i = 0; i < 16; i++) {
        int f = threadIdx.x + i * 256;
        int d = f >> 6, ss = f & 63;
        size_t g = base + (size_t)d * Sv + s0 + ss;
        Th[g] = t[0][ss][d];
        Tl[g] = t[1][ss][d];
    }
}

// =====================================================================
// attention scores (tensorized): P = Q K^T / 8, 64x64 tiles, causal skip
// =====================================================================
__global__ void __launch_bounds__(128) attn_scores_mma() {
    int bh = blockIdx.z;
    int q0 = blockIdx.y * 64, k0 = blockIdx.x * 64;
    if (k0 > q0 + 63) return;
    __shared__ __align__(16) uint8_t sQ[2][9216];   // [hi/lo][64 rows * 144B]
    __shared__ __align__(16) uint8_t sK[2][9216];

    int tid = threadIdx.x, lane = tid & 31, w = tid >> 5;
    size_t base = (size_t)bh * Sv * HDv;
    uint32_t qS = smem_to_u32(&sQ[0][0]);
    uint32_t kS = smem_to_u32(&sK[0][0]);

    #pragma unroll
    for (int i = 0; i < 4; i++) {
        int f = tid + i * 128;
        int row = f >> 3, seg = f & 7;
        uint32_t so = (uint32_t)(row * 144 + seg * 16);
        size_t gq = base + (size_t)(q0 + row) * HDv + seg * 8;
        size_t gk = base + (size_t)(k0 + row) * HDv + seg * 8;
        CP_ASYNC16(qS + so,        g_Qh + gq);
        CP_ASYNC16(qS + 9216 + so, g_Ql + gq);
        CP_ASYNC16(kS + so,        g_Kh + gk);
        CP_ASYNC16(kS + 9216 + so, g_Kl + gk);
    }
    CP_COMMIT(); CP_WAIT0();
    __syncthreads();

    float acc[8][4];
    #pragma unroll
    for (int nj = 0; nj < 8; nj++)
        #pragma unroll
        for (int q = 0; q < 4; q++) acc[nj][q] = 0.f;

    int a_row = lane & 15, a_chunk = lane >> 4;
    int b_row = (lane & 7) | ((lane >> 4) << 3);
    int b_chunk = (lane >> 3) & 1;
    uint32_t aB = qS + (uint32_t)((w * 16 + a_row) * 144 + a_chunk * 16);
    uint32_t bB = kS + (uint32_t)(b_row * 144 + b_chunk * 16);

    #pragma unroll
    for (int ks = 0; ks < 4; ks++) {
        uint32_t ah[4], al[4];
        LDSM_X4(ah[0], ah[1], ah[2], ah[3], aB + ks * 32u);
        LDSM_X4(al[0], al[1], al[2], al[3], aB + 9216u + ks * 32u);
        #pragma unroll
        for (int g = 0; g < 4; g++) {
            uint32_t b0, b1, b2, b3;
            LDSM_X4(b0, b1, b2, b3, bB + g * 2304u + ks * 32u);
            MMA_BF16(acc[2*g],   ah[0], ah[1], ah[2], ah[3], b0, b1);
            MMA_BF16(acc[2*g+1], ah[0], ah[1], ah[2], ah[3], b2, b3);
            MMA_BF16(acc[2*g],   al[0], al[1], al[2], al[3], b0, b1);
            MMA_BF16(acc[2*g+1], al[0], al[1], al[2], al[3], b2, b3);
            LDSM_X4(b0, b1, b2, b3, bB + 9216u + g * 2304u + ks * 32u);
            MMA_BF16(acc[2*g],   ah[0], ah[1], ah[2], ah[3], b0, b1);
            MMA_BF16(acc[2*g+1], ah[0], ah[1], ah[2], ah[3], b2, b3);
        }
    }

    float* out = g_P + (size_t)bh * Sv * Sv;
    int crow = lane >> 2, ccol = (lane & 3) * 2;
    int qq = q0 + w * 16 + crow;
    #pragma unroll
    for (int nj = 0; nj < 8; nj++) {
        int kk = k0 + nj * 8 + ccol;
        out[(size_t)qq * Sv + kk]       = acc[nj][0] * 0.125f;
        out[(size_t)qq * Sv + kk + 1]   = acc[nj][1] * 0.125f;
        out[(size_t)(qq+8) * Sv + kk]   = acc[nj][2] * 0.125f;
        out[(size_t)(qq+8) * Sv + kk+1] = acc[nj][3] * 0.125f;
    }
}

// ---------------- causal softmax: fp32 scores -> bf16 hi/lo probs ----------------
__global__ void __launch_bounds__(256) attn_softmax_k() {
    __shared__ float red[8];
    int idx = blockIdx.x;            // bh*S + q
    int q = idx & (Sv - 1);
    float* row = g_P + (size_t)idx * Sv;
    int len = q + 1;
    int kup = ((q >> 6) + 1) << 6;
    int tid = threadIdx.x;
    float mx = -1e30f;
    for (int k = tid; k < len; k += 256) mx = fmaxf(mx, row[k]);
    mx = block_max(mx, red);
    float sum = 0.f;
    for (int k = tid; k < len; k += 256) {
        float e = expf(row[k] - mx);
        row[k] = e;
        sum += e;
    }
    sum = block_sum(sum, red);
    float inv = 1.0f / sum;
    for (int k = tid; k < kup; k += 256) {
        float p = (k < len) ? row[k] * inv : 0.0f;
        __nv_bfloat16 ph = __float2bfloat16(p);
        g_Phi[(size_t)idx * Sv + k] = ph;
        g_Plo[(size_t)idx * Sv + k] = __float2bfloat16(p - __bfloat162float(ph));
    }
}

// =====================================================================
// PV (tensorized): AO[q][d] = P[q][k] * VT[d][k], causal K-bound.
// =====================================================================
__global__ void __launch_bounds__(128) attn_pv_mma() {
    int bh = blockIdx.y;
    int q0 = blockIdx.x * 64;
    __shared__ __align__(16) uint8_t sP[2][9216];
    __shared__ __align__(16) uint8_t sV[2][9216];

    int tid = threadIdx.x, lane = tid & 31, w = tid >> 5;
    size_t pBase = (size_t)(bh * Sv) * Sv;
    size_t vBase = (size_t)bh * Sv * HDv;
    uint32_t pS = smem_to_u32(&sP[0][0]);
    uint32_t vS = smem_to_u32(&sV[0][0]);

    float acc[8][4];
    #pragma unroll
    for (int nj = 0; nj < 8; nj++)
        #pragma unroll
        for (int q = 0; q < 4; q++) acc[nj][q] = 0.f;

    int a_row = lane & 15, a_chunk = lane >> 4;
    int b_row = (lane & 7) | ((lane >> 4) << 3);
    int b_chunk = (lane >> 3) & 1;
    uint32_t aB = pS + (uint32_t)((w * 16 + a_row) * 144 + a_chunk * 16);
    uint32_t bB = vS + (uint32_t)(b_row * 144 + b_chunk * 16);

    int kmax = q0 + 64;
    for (int kc = 0; kc < kmax; kc += 64) {
        #pragma unroll
        for (int i = 0; i < 4; i++) {
            int f = tid + i * 128;
            int row = f >> 3, seg = f & 7;
            uint32_t so = (uint32_t)(row * 144 + seg * 16);
            size_t gp = pBase + (size_t)(q0 + row) * Sv + kc + seg * 8;
            size_t gv = vBase + (size_t)row * Sv + kc + seg * 8;
            CP_ASYNC16(pS + so,        g_Phi + gp);
            CP_ASYNC16(pS + 9216 + so, g_Plo + gp);
            CP_ASYNC16(vS + so,        g_VTh + gv);
            CP_ASYNC16(vS + 9216 + so, g_VTl + gv);
        }
        CP_COMMIT(); CP_WAIT0();
        __syncthreads();

        #pragma unroll
        for (int ks = 0; ks < 4; ks++) {
            uint32_t ah[4], al[4];
            LDSM_X4(ah[0], ah[1], ah[2], ah[3], aB + ks * 32u);
            LDSM_X4(al[0], al[1], al[2], al[3], aB + 9216u + ks * 32u);
            #pragma unroll
            for (int g = 0; g < 4; g++) {
                uint32_t b0, b1, b2, b3;
                LDSM_X4(b0, b1, b2, b3, bB + g * 2304u + ks * 32u);
                MMA_BF16(acc[2*g],   ah[0], ah[1], ah[2], ah[3], b0, b1);
                MMA_BF16(acc[2*g+1], ah[0], ah[1], ah[2], ah[3], b2, b3);
                MMA_BF16(acc[2*g],   al[0], al[1], al[2], al[3], b0, b1);
                MMA_BF16(acc[2*g+1], al[0], al[1], al[2], al[3], b2, b3);
                LDSM_X4(b0, b1, b2, b3, bB + 9216u + g * 2304u + ks * 32u);
                MMA_BF16(acc[2*g],   ah[0], ah[1], ah[2], ah[3], b0, b1);
                MMA_BF16(acc[2*g+1], ah[0], ah[1], ah[2], ah[3], b2, b3);
            }
        }
        __syncthreads();
    }

    int b = bh >> 4, h = bh & 15;
    int crow = lane >> 2, ccol = (lane & 3) * 2;
    int q = q0 + w * 16 + crow;
    #pragma unroll
    for (int nj = 0; nj < 8; nj++) {
        int d = nj * 8 + ccol;
        uint32_t hi, lo;
        split2(acc[nj][0], acc[nj][1], hi, lo);
        size_t o0 = (size_t)(b * Sv + q) * Tv + h * 64 + d;
        *(uint32_t*)&g_Ahi[o0] = hi;
        *(uint32_t*)&g_Alo[o0] = lo;
        split2(acc[nj][2], acc[nj][3], hi, lo);
        size_t o1 = (size_t)(b * Sv + q + 8) * Tv + h * 64 + d;
        *(uint32_t*)&g_Ahi[o1] = hi;
        *(uint32_t*)&g_Alo[o1] = lo;
    }
}

// ---------------- launch (kernel launches ONLY) ----------------
extern "C" void kernel_launch(void* const* d_in, const int* in_sizes, int n_in,
                              void* d_out, int out_size) {
    const int*   ids = (const int*)  d_in[0];
    const float* emb = (const float*)d_in[1];
    const float* Wu  = (const float*)d_in[2];
    const float* Wo  = (const float*)d_in[3];
    const float* n1w = (const float*)d_in[4];
    const float* n1b = (const float*)d_in[5];
    const float* n2w = (const float*)d_in[6];
    const float* n2b = (const float*)d_in[7];
    const float* f1w = (const float*)d_in[8];
    const float* f1b = (const float*)d_in[9];
    const float* f2w = (const float*)d_in[10];
    const float* f2b = (const float*)d_in[11];
    const float* fnw = (const float*)d_in[12];
    const float* fnb = (const float*)d_in[13];
    float* out = (float*)d_out;

    // front-load so the QKV gemm is launch #4 (ncu capture window)
    embed_k<<<BS, 256>>>(ids, emb);
    conv_w_k<<<(int)((N_WU/4  + 255) / 256), 256>>>(Wu,  OFF_WU,  (int)(N_WU/4));
    layernorm_split_k<<<BS, 256>>>(n1w, n1b);
    gemm_mma<false, false, false, false><<<dim3(BS / 128, 3 * Tv / 128), 256>>>(
        OFF_WU, nullptr, nullptr, SEL_U, 0, BS, 3 * Tv, Dv);
    conv_w_k<<<(int)((N_WO/4  + 255) / 256), 256>>>(Wo,  OFF_WO,  (int)(N_WO/4));
    conv_w_k<<<(int)((N_F1/4  + 255) / 256), 256>>>(f1w, OFF_F1,  (int)(N_F1/4));
    conv_w_k<<<(int)((N_F2/4  + 255) / 256), 256>>>(f2w, OFF_F2,  (int)(N_F2/4));
    conv_w_k<<<(int)((N_EMB/4 + 255) / 256), 256>>>(emb, OFF_EMB, (int)(N_EMB/4));

    for (int l = 0; l < Lv; l++) {
        if (l > 0) {
            layernorm_split_k<<<BS, 256>>>(n1w + l * Dv, n1b + l * Dv);
            gemm_mma<false, false, false, false><<<dim3(BS / 128, 3 * Tv / 128), 256>>>(
                OFF_WU + (size_t)l * 3 * Tv * Dv, nullptr, nullptr, SEL_U, 0, BS, 3 * Tv, Dv);
        }
        qkv_rope_k<<<(BHv * Sv * HDv) / 256, 256>>>();
        vT_k<<<dim3(Sv / 64, BHv), 256>>>();
        attn_scores_mma<<<dim3(Sv / 64, Sv / 64, BHv), 128>>>();
        attn_softmax_k<<<BHv * Sv, 256>>>();
        attn_pv_mma<<<dim3(Sv / 64, BHv), 128>>>();
        gemm_mma<false, false, true, false><<<dim3(BS / 128, Dv / 128), 256>>>(
            OFF_WO + (size_t)l * Dv * Tv, nullptr, nullptr, SEL_X, 0, BS, Dv, Tv);

        layernorm_split_k<<<BS, 256>>>(n2w + l * Dv, n2b + l * Dv);
        gemm_mma<true, true, false, true><<<dim3(BS / 128, FFv / 128), 256>>>(
            OFF_F1 + (size_t)l * FFv * Dv, f1b + (size_t)l * FFv, nullptr, -1, 0, BS, FFv, Dv);
        gemm_mma<true, false, true, false><<<dim3(BS / 128, Dv / 128), 256>>>(
            OFF_F2 + (size_t)l * Dv * FFv, f2b + (size_t)l * Dv, nullptr, SEL_X, 1, BS, Dv, FFv);
    }

    // ---- final LN + tied-embedding logits ----
    layernorm_split_k<<<BS, 256>>>(fnw, fnb);
    gemm_mma<false, false, false, false><<<dim3(BS / 128, Vv / 128), 256>>>(
        OFF_EMB, nullptr, out, -1, 0, BS, Vv, Dv);
}